// round 1
// baseline (speedup 1.0000x reference)
#include <cuda_runtime.h>
#include <cstdint>

#define K_DIM 64
#define BM 128
#define BN 64
#define LDA 68
#define LDB 68
#define NTHREADS 256

__device__ __forceinline__ unsigned f2tf32(float x) {
    unsigned r;
    asm("cvt.rna.tf32.f32 %0, %1;" : "=r"(r) : "f"(x));
    return r;
}

__global__ void init_kernel(float* out) { out[0] = 0.0f; }

// Computes pref = sel @ item_emb^T (tf32 tensor path), writes pref to out+1,
// and accumulates sum(pref^2) into out[0] via per-block atomics.
__global__ void __launch_bounds__(NTHREADS, 2) mf_gemm_kernel(
    const float* __restrict__ user_emb,
    const float* __restrict__ item_emb,
    const int* __restrict__ uid,
    float* __restrict__ out,
    int Nitems)
{
    extern __shared__ float smem[];
    unsigned* Asu = (unsigned*)smem;               // BM x LDA (tf32 bit patterns)
    unsigned* Bsu = (unsigned*)(smem + BM * LDA);  // BN x LDB

    const int n0 = blockIdx.x * BN;
    const int m0 = blockIdx.y * BM;
    const int t  = threadIdx.x;

    // Gather A rows (user_emb[center_uid]) -> smem, converted to tf32 (RN).
    #pragma unroll
    for (int i = t; i < BM * 16; i += NTHREADS) {
        int r = i >> 4, s = i & 15;
        int u = uid[m0 + r];
        float4 v = *(const float4*)(user_emb + (size_t)u * K_DIM + s * 4);
        uint4 w = make_uint4(f2tf32(v.x), f2tf32(v.y), f2tf32(v.z), f2tf32(v.w));
        *(uint4*)(Asu + r * LDA + s * 4) = w;
    }
    // Load B tile (item_emb rows), zero-fill past Nitems.
    #pragma unroll
    for (int i = t; i < BN * 16; i += NTHREADS) {
        int r = i >> 4, s = i & 15;
        int n = n0 + r;
        float4 v = make_float4(0.f, 0.f, 0.f, 0.f);
        if (n < Nitems) v = *(const float4*)(item_emb + (size_t)n * K_DIM + s * 4);
        uint4 w = make_uint4(f2tf32(v.x), f2tf32(v.y), f2tf32(v.z), f2tf32(v.w));
        *(uint4*)(Bsu + r * LDB + s * 4) = w;
    }
    __syncthreads();

    const int lane = t & 31, wid = t >> 5;
    const int g = lane >> 2, tig = lane & 3;   // groupID, thread-in-group
    const int wm = (wid >> 1) * 32;            // warp m-offset: 0,32,64,96
    const int wn = (wid & 1) * 32;             // warp n-offset: 0,32

    float acc[2][4][4];
    #pragma unroll
    for (int mi = 0; mi < 2; mi++)
        #pragma unroll
        for (int ni = 0; ni < 4; ni++)
            #pragma unroll
            for (int q = 0; q < 4; q++) acc[mi][ni][q] = 0.f;

    #pragma unroll
    for (int kk = 0; kk < 8; kk++) {
        const int k0 = kk * 8;
        unsigned a[2][4], b[4][2];
        #pragma unroll
        for (int mi = 0; mi < 2; mi++) {
            int r0 = wm + mi * 16 + g;
            a[mi][0] = Asu[r0 * LDA + k0 + tig];
            a[mi][1] = Asu[(r0 + 8) * LDA + k0 + tig];
            a[mi][2] = Asu[r0 * LDA + k0 + tig + 4];
            a[mi][3] = Asu[(r0 + 8) * LDA + k0 + tig + 4];
        }
        #pragma unroll
        for (int ni = 0; ni < 4; ni++) {
            int c = wn + ni * 8 + g;
            b[ni][0] = Bsu[c * LDB + k0 + tig];
            b[ni][1] = Bsu[c * LDB + k0 + tig + 4];
        }
        #pragma unroll
        for (int mi = 0; mi < 2; mi++)
            #pragma unroll
            for (int ni = 0; ni < 4; ni++)
                asm volatile(
                    "mma.sync.aligned.m16n8k8.row.col.f32.tf32.tf32.f32 "
                    "{%0,%1,%2,%3}, {%4,%5,%6,%7}, {%8,%9}, {%0,%1,%2,%3};\n"
                    : "+f"(acc[mi][ni][0]), "+f"(acc[mi][ni][1]),
                      "+f"(acc[mi][ni][2]), "+f"(acc[mi][ni][3])
                    : "r"(a[mi][0]), "r"(a[mi][1]), "r"(a[mi][2]), "r"(a[mi][3]),
                      "r"(b[ni][0]), "r"(b[ni][1]));
    }

    // Epilogue: store pref (scalar STG.32 — out+1 breaks 8B alignment) and
    // accumulate sum of squares for the loss.
    float* pref = out + 1;
    float ls = 0.f;
    #pragma unroll
    for (int mi = 0; mi < 2; mi++) {
        int r0 = m0 + wm + mi * 16 + g;
        #pragma unroll
        for (int ni = 0; ni < 4; ni++) {
            int c0 = n0 + wn + ni * 8 + tig * 2;
            if (c0 < Nitems) {   // c0 even, Nitems even -> c0+1 also valid
                float v0 = acc[mi][ni][0], v1 = acc[mi][ni][1];
                float v2 = acc[mi][ni][2], v3 = acc[mi][ni][3];
                size_t base0 = (size_t)r0 * Nitems + c0;
                size_t base1 = (size_t)(r0 + 8) * Nitems + c0;
                pref[base0] = v0; pref[base0 + 1] = v1;
                pref[base1] = v2; pref[base1 + 1] = v3;
                ls += v0 * v0 + v1 * v1 + v2 * v2 + v3 * v3;
            }
        }
    }

    // Block-level loss reduction -> single atomic per block.
    #pragma unroll
    for (int o = 16; o; o >>= 1) ls += __shfl_xor_sync(0xffffffffu, ls, o);
    __shared__ float wls[NTHREADS / 32];
    if (lane == 0) wls[wid] = ls;
    __syncthreads();
    if (t == 0) {
        float s = 0.f;
        #pragma unroll
        for (int i = 0; i < NTHREADS / 32; i++) s += wls[i];
        atomicAdd(out, s);
    }
}

// loss += sum over DISTINCT (b, seq[b,h]) of (1 - 2*pref[b,item]).
// Set semantics of the reference scatter are replicated via in-smem dedup.
__global__ void positives_kernel(
    const float* __restrict__ user_emb,
    const float* __restrict__ item_emb,
    const int* __restrict__ uid,
    const int* __restrict__ seq,
    float* __restrict__ out,
    int HIST)
{
    __shared__ float u[K_DIM];
    __shared__ int s_seq[128];
    __shared__ int s_dup[128];
    int b = blockIdx.x, t = threadIdx.x;  // 64 threads
    u[t] = user_emb[(size_t)uid[b] * K_DIM + t];
    if (t < HIST) s_seq[t] = seq[b * HIST + t];
    __syncthreads();
    if (t < HIST) {
        int it = s_seq[t], dup = 0;
        for (int j = 0; j < t; j++) dup |= (s_seq[j] == it);
        s_dup[t] = dup;
    }
    __syncthreads();
    int lane = t & 31, w = t >> 5;
    float local = 0.f;
    for (int h = w; h < HIST; h += 2) {
        if (!s_dup[h]) {
            size_t base = (size_t)s_seq[h] * K_DIM;
            float d = u[lane] * item_emb[base + lane]
                    + u[lane + 32] * item_emb[base + lane + 32];
            #pragma unroll
            for (int o = 16; o; o >>= 1) d += __shfl_xor_sync(0xffffffffu, d, o);
            if (lane == 0) local += 1.0f - 2.0f * d;
        }
    }
    if (lane == 0) atomicAdd(out, local);
}

extern "C" void kernel_launch(void* const* d_in, const int* in_sizes, int n_in,
                              void* d_out, int out_size) {
    const float* user_emb = (const float*)d_in[0];
    const float* item_emb = (const float*)d_in[1];
    const int*   uid      = (const int*)d_in[2];
    const int*   seq      = (const int*)d_in[3];
    float* out = (float*)d_out;

    int B    = in_sizes[2];
    int N    = in_sizes[1] / K_DIM;
    int HIST = in_sizes[3] / B;

    size_t smem_bytes = (size_t)(BM * LDA + BN * LDB) * sizeof(float);
    cudaFuncSetAttribute(mf_gemm_kernel,
                         cudaFuncAttributeMaxDynamicSharedMemorySize,
                         (int)smem_bytes);

    init_kernel<<<1, 1>>>(out);

    dim3 grid((N + BN - 1) / BN, B / BM);
    mf_gemm_kernel<<<grid, NTHREADS, smem_bytes>>>(user_emb, item_emb, uid, out, N);

    positives_kernel<<<B, K_DIM>>>(user_emb, item_emb, uid, seq, out, HIST);
}